// round 13
// baseline (speedup 1.0000x reference)
#include <cuda_runtime.h>

// CounterfactualMultiheadAttention — algebraically collapsed, single fused kernel.
//   attn_weights[b,h,q,k] = !mask[b,k] / cnt_b          (independent of h,q,Q,K)
//   output[b,q,:] = ((colsum_value[b] @ Wv^T)/cnt_b + bv) @ Wo^T + bo   (independent of q)
// Blocks [128,1152): stream the 256 MB attn broadcast from t=0 (the real cost,
// ~6.3 TB/s LTS cap). Blocks [0,128): colsum -> gemv_v -> gemv_o -> 16 MB out
// write, synchronized among themselves by a monotonic ticket barrier; their
// 24 MB of reads hide under the store stream. Grid = 1152 blocks = exactly one
// wave at 8 blocks/SM (warp-limited), so all blocks are co-resident.

#define B 4
#define L 1024
#define D 1024
#define H 16
#define ROWCHUNKS 8
#define NPREFIX 128             // prefix blocks (<= 148 SMs; always wave-1)
#define NBLK_ATTN 1024          // attn writer blocks (2^24 float4 / 16384)

__device__ float g_partial[B][ROWCHUNKS][D];
__device__ float g_ctx[B][D];
__device__ float g_outrow[B][D];
__device__ unsigned int g_bar[3];   // monotonic tickets; never reset

// mask dtype decode: mode 0=int32, 1=uint8, 2=float32
__device__ __forceinline__ bool mask_test(const void* mask, int mode, int g) {
    if (mode == 2) return ((const float*)mask)[g] != 0.0f;
    if (mode == 1) return ((const unsigned char*)mask)[g] != 0;
    return ((const int*)mask)[g] != 0;
}

// Per-block dtype probe over bytes [0,4096) (in-bounds for all 3 dtypes).
// float32 1.0f = 00 00 80 3F -> 0x3F at p%4==3; uint8 -> nonzero at p%4!=0.
// Deterministic for this dataset (mask = randint(0,2): both values present).
__device__ __forceinline__ void probe_flags(const void* mask, int tid,
                                            int* sFloat, int* sOff) {
    const unsigned char* bytes = (const unsigned char*)mask;
    int f = 0, o = 0;
#pragma unroll
    for (int i = 0; i < 16; i++) {
        unsigned char v = bytes[tid * 16 + i];
        int r = i & 3;
        if (r == 3 && v == 0x3F) f = 1;
        if (r != 0 && v != 0)    o = 1;
    }
    if (f) atomicOr(sFloat, 1);
    if (o) atomicOr(sOff, 1);
}

// Grid barrier among the NPREFIX prefix blocks only. Monotonic ticket counter:
// base = ticket rounded down to a multiple of NPREFIX; wait until all NPREFIX
// tickets of this launch arrived. Wrap-safe (unsigned difference). Release via
// threadfence before the add; acquire via threadfence after the spin.
// Deadlock-free: prefix blocks (blockIdx 0..127) are dispatched first and are
// always wave-1 resident; attn blocks never wait on this barrier.
__device__ __forceinline__ void prefix_barrier(unsigned int* ctr) {
    __syncthreads();
    if (threadIdx.x == 0) {
        __threadfence();                                   // release
        unsigned int ticket = atomicAdd(ctr, 1u);
        unsigned int base = ticket - (ticket & (NPREFIX - 1));
        while ((*(volatile unsigned int*)ctr) - base < NPREFIX)
            __nanosleep(64);
        __threadfence();                                   // acquire
    }
    __syncthreads();
}

// ---------------------------------------------------------------------------
__global__ void __launch_bounds__(256)
k_fused(const float* __restrict__ value, const void* __restrict__ mask,
        const float* __restrict__ Wv, const float* __restrict__ bv,
        const float* __restrict__ Wo, const float* __restrict__ bo,
        float4* __restrict__ out, float4* __restrict__ attn) {
    __shared__ int sFloat, sOff, sCnt;
    __shared__ int scnt[B];
    __shared__ float4 sh[B][256];
    const int tid = threadIdx.x;
    if (tid == 0) { sFloat = 0; sOff = 0; sCnt = 0; }
    if (tid < B) scnt[tid] = 0;
    __syncthreads();
    probe_flags(mask, tid, &sFloat, &sOff);
    __syncthreads();
    const int mode = sFloat ? 2 : (sOff ? 1 : 0);

    if (blockIdx.x >= NPREFIX) {
        // ---- attn writer: 16384 consecutive float4, all within one batch ---
        const unsigned abi = blockIdx.x - NPREFIX;
        const int b = abi >> 8;                     // 256 blocks per batch
        const bool m0 = mask_test(mask, mode, b * L + tid * 4 + 0);
        const bool m1 = mask_test(mask, mode, b * L + tid * 4 + 1);
        const bool m2 = mask_test(mask, mode, b * L + tid * 4 + 2);
        const bool m3 = mask_test(mask, mode, b * L + tid * 4 + 3);
        int cnt = (!m0) + (!m1) + (!m2) + (!m3);    // 256 threads cover the row
        atomicAdd(&sCnt, cnt);
        __syncthreads();
        const float inv = 1.0f / (float)max(sCnt, 1);
        const float4 v = make_float4(m0 ? 0.0f : inv, m1 ? 0.0f : inv,
                                     m2 ? 0.0f : inv, m3 ? 0.0f : inv);
        float4* p = attn + abi * 16384u + tid;      // per-thread k4 == tid
#pragma unroll
        for (int j = 0; j < 64; j++)
            __stcs(p + j * 256u, v);
        return;
    }

    // ======================= prefix block (0..127) ==========================
    const int lane = tid & 31, warp = tid >> 5;

    // counts per batch (each thread's 16 entries lie in batch tid>>6)
    {
        int c = 0;
#pragma unroll
        for (int i = 0; i < 16; i++)
            c += mask_test(mask, mode, tid * 16 + i) ? 0 : 1;
        atomicAdd(&scnt[tid >> 6], c);
    }

    // ---- phase 1: masked partial column-sum (block = one of 128 partials) --
    {
        const int cb = blockIdx.x;
        const int c  = (cb & 3) * 256 + tid;
        const int rc = (cb >> 2) & 7;
        const int b  = cb >> 5;
        const float* vp = value + ((size_t)b * L + rc * 128) * D + c;
        const int gbase = b * L + rc * 128;
        float s = 0.0f;
#pragma unroll 8
        for (int r = 0; r < 128; r++) {
            float nz = mask_test(mask, mode, gbase + r) ? 0.0f : 1.0f;
            s += vp[(size_t)r * D] * nz;
        }
        g_partial[b][rc][c] = s;
    }
    prefix_barrier(&g_bar[0]);

    // ---- phase 2: gemv vs Wv (block handles 8 rows; vector in smem) --------
#pragma unroll
    for (int b = 0; b < B; b++) {
        float4 a = make_float4(0.f, 0.f, 0.f, 0.f);
#pragma unroll
        for (int rc = 0; rc < ROWCHUNKS; rc++) {
            float4 p = ((const float4*)g_partial[b][rc])[tid];
            a.x += p.x; a.y += p.y; a.z += p.z; a.w += p.w;
        }
        sh[b][tid] = a;
    }
    __syncthreads();
    {
        const int row = blockIdx.x * 8 + warp;
        const float4* wr = (const float4*)(Wv + (size_t)row * D);
        float a0 = 0, a1 = 0, a2 = 0, a3 = 0;
#pragma unroll
        for (int j = 0; j < 8; j++) {
            float4 w  = wr[lane + j * 32];
            float4 x0 = sh[0][lane + j * 32];
            float4 x1 = sh[1][lane + j * 32];
            float4 x2 = sh[2][lane + j * 32];
            float4 x3 = sh[3][lane + j * 32];
            a0 += w.x * x0.x + w.y * x0.y + w.z * x0.z + w.w * x0.w;
            a1 += w.x * x1.x + w.y * x1.y + w.z * x1.z + w.w * x1.w;
            a2 += w.x * x2.x + w.y * x2.y + w.z * x2.z + w.w * x2.w;
            a3 += w.x * x3.x + w.y * x3.y + w.z * x3.z + w.w * x3.w;
        }
#pragma unroll
        for (int off = 16; off; off >>= 1) {
            a0 += __shfl_down_sync(0xFFFFFFFFu, a0, off);
            a1 += __shfl_down_sync(0xFFFFFFFFu, a1, off);
            a2 += __shfl_down_sync(0xFFFFFFFFu, a2, off);
            a3 += __shfl_down_sync(0xFFFFFFFFu, a3, off);
        }
        if (lane == 0) {
            float bb = bv[row];
            g_ctx[0][row] = a0 / (float)max(scnt[0], 1) + bb;
            g_ctx[1][row] = a1 / (float)max(scnt[1], 1) + bb;
            g_ctx[2][row] = a2 / (float)max(scnt[2], 1) + bb;
            g_ctx[3][row] = a3 / (float)max(scnt[3], 1) + bb;
        }
    }
    prefix_barrier(&g_bar[1]);

    // ---- phase 3: gemv vs Wo ----------------------------------------------
#pragma unroll
    for (int b = 0; b < B; b++)
        sh[b][tid] = ((const float4*)g_ctx[b])[tid];
    __syncthreads();
    {
        const int row = blockIdx.x * 8 + warp;
        const float4* wr = (const float4*)(Wo + (size_t)row * D);
        float a0 = 0, a1 = 0, a2 = 0, a3 = 0;
#pragma unroll
        for (int j = 0; j < 8; j++) {
            float4 w  = wr[lane + j * 32];
            float4 x0 = sh[0][lane + j * 32];
            float4 x1 = sh[1][lane + j * 32];
            float4 x2 = sh[2][lane + j * 32];
            float4 x3 = sh[3][lane + j * 32];
            a0 += w.x * x0.x + w.y * x0.y + w.z * x0.z + w.w * x0.w;
            a1 += w.x * x1.x + w.y * x1.y + w.z * x1.z + w.w * x1.w;
            a2 += w.x * x2.x + w.y * x2.y + w.z * x2.z + w.w * x2.w;
            a3 += w.x * x3.x + w.y * x3.y + w.z * x3.z + w.w * x3.w;
        }
#pragma unroll
        for (int off = 16; off; off >>= 1) {
            a0 += __shfl_down_sync(0xFFFFFFFFu, a0, off);
            a1 += __shfl_down_sync(0xFFFFFFFFu, a1, off);
            a2 += __shfl_down_sync(0xFFFFFFFFu, a2, off);
            a3 += __shfl_down_sync(0xFFFFFFFFu, a3, off);
        }
        if (lane == 0) {
            float bb = bo[row];
            g_outrow[0][row] = a0 + bb;
            g_outrow[1][row] = a1 + bb;
            g_outrow[2][row] = a2 + bb;
            g_outrow[3][row] = a3 + bb;
        }
    }
    prefix_barrier(&g_bar[2]);

    // ---- phase 4: 16 MB output broadcast (8192 float4 per block) ----------
    {
        const int b = blockIdx.x >> 5;             // 32 blocks per batch
        const float4 v = ((const float4*)g_outrow[b])[tid];
        float4* p = out + blockIdx.x * 8192u + tid;
#pragma unroll
        for (int j = 0; j < 32; j++)
            __stcs(p + j * 256u, v);
    }
}

// ---------------- Fallback path for unexpected out_size ---------------------
__global__ void __launch_bounds__(256)
k_colsum(const float* __restrict__ value, const void* __restrict__ mask) {
    __shared__ int sFloat, sOff;
    const int tid = threadIdx.x;
    if (tid == 0) { sFloat = 0; sOff = 0; }
    __syncthreads();
    probe_flags(mask, tid, &sFloat, &sOff);
    __syncthreads();
    const int mode = sFloat ? 2 : (sOff ? 1 : 0);
    const int cb = blockIdx.x;
    const int c  = (cb & 3) * 256 + tid;
    const int rc = (cb >> 2) & 7;
    const int b  = cb >> 5;
    const float* vp = value + ((size_t)b * L + rc * 128) * D + c;
    const int gbase = b * L + rc * 128;
    float s = 0.0f;
    for (int r = 0; r < 128; r++) {
        float nz = mask_test(mask, mode, gbase + r) ? 0.0f : 1.0f;
        s += vp[(size_t)r * D] * nz;
    }
    g_partial[b][rc][c] = s;
}

__global__ void __launch_bounds__(256)
k_gemv_v(const float* __restrict__ Wv, const float* __restrict__ bv,
         const void* __restrict__ mask) {
    __shared__ int sFloat, sOff;
    __shared__ int scnt[B];
    __shared__ float4 sh[B][256];
    const int tid = threadIdx.x, lane = tid & 31, warp = tid >> 5;
    if (tid == 0) { sFloat = 0; sOff = 0; }
    if (tid < B) scnt[tid] = 0;
    __syncthreads();
    probe_flags(mask, tid, &sFloat, &sOff);
    __syncthreads();
    const int mode = sFloat ? 2 : (sOff ? 1 : 0);
    {
        int c = 0;
        for (int i = 0; i < 16; i++)
            c += mask_test(mask, mode, tid * 16 + i) ? 0 : 1;
        atomicAdd(&scnt[tid >> 6], c);
    }
    for (int b = 0; b < B; b++) {
        float4 a = make_float4(0.f, 0.f, 0.f, 0.f);
        for (int rc = 0; rc < ROWCHUNKS; rc++) {
            float4 p = ((const float4*)g_partial[b][rc])[tid];
            a.x += p.x; a.y += p.y; a.z += p.z; a.w += p.w;
        }
        sh[b][tid] = a;
    }
    __syncthreads();
    const int row = blockIdx.x * 8 + warp;
    const float4* wr = (const float4*)(Wv + (size_t)row * D);
    float a0 = 0, a1 = 0, a2 = 0, a3 = 0;
    for (int j = 0; j < 8; j++) {
        float4 w  = wr[lane + j * 32];
        float4 x0 = sh[0][lane + j * 32], x1 = sh[1][lane + j * 32];
        float4 x2 = sh[2][lane + j * 32], x3 = sh[3][lane + j * 32];
        a0 += w.x * x0.x + w.y * x0.y + w.z * x0.z + w.w * x0.w;
        a1 += w.x * x1.x + w.y * x1.y + w.z * x1.z + w.w * x1.w;
        a2 += w.x * x2.x + w.y * x2.y + w.z * x2.z + w.w * x2.w;
        a3 += w.x * x3.x + w.y * x3.y + w.z * x3.z + w.w * x3.w;
    }
    for (int off = 16; off; off >>= 1) {
        a0 += __shfl_down_sync(0xFFFFFFFFu, a0, off);
        a1 += __shfl_down_sync(0xFFFFFFFFu, a1, off);
        a2 += __shfl_down_sync(0xFFFFFFFFu, a2, off);
        a3 += __shfl_down_sync(0xFFFFFFFFu, a3, off);
    }
    if (lane == 0) {
        float bb = bv[row];
        g_ctx[0][row] = a0 / (float)max(scnt[0], 1) + bb;
        g_ctx[1][row] = a1 / (float)max(scnt[1], 1) + bb;
        g_ctx[2][row] = a2 / (float)max(scnt[2], 1) + bb;
        g_ctx[3][row] = a3 / (float)max(scnt[3], 1) + bb;
    }
}

__global__ void __launch_bounds__(256)
k_gemv_o(const float* __restrict__ Wo, const float* __restrict__ bo) {
    __shared__ float4 sh[B][256];
    const int tid = threadIdx.x, lane = tid & 31, warp = tid >> 5;
    for (int b = 0; b < B; b++)
        sh[b][tid] = ((const float4*)g_ctx[b])[tid];
    __syncthreads();
    const int row = blockIdx.x * 8 + warp;
    const float4* wr = (const float4*)(Wo + (size_t)row * D);
    float a0 = 0, a1 = 0, a2 = 0, a3 = 0;
    for (int j = 0; j < 8; j++) {
        float4 w  = wr[lane + j * 32];
        float4 x0 = sh[0][lane + j * 32], x1 = sh[1][lane + j * 32];
        float4 x2 = sh[2][lane + j * 32], x3 = sh[3][lane + j * 32];
        a0 += w.x * x0.x + w.y * x0.y + w.z * x0.z + w.w * x0.w;
        a1 += w.x * x1.x + w.y * x1.y + w.z * x1.z + w.w * x1.w;
        a2 += w.x * x2.x + w.y * x2.y + w.z * x2.z + w.w * x2.w;
        a3 += w.x * x3.x + w.y * x3.y + w.z * x3.z + w.w * x3.w;
    }
    for (int off = 16; off; off >>= 1) {
        a0 += __shfl_down_sync(0xFFFFFFFFu, a0, off);
        a1 += __shfl_down_sync(0xFFFFFFFFu, a1, off);
        a2 += __shfl_down_sync(0xFFFFFFFFu, a2, off);
        a3 += __shfl_down_sync(0xFFFFFFFFu, a3, off);
    }
    if (lane == 0) {
        float bb = bo[row];
        g_outrow[0][row] = a0 + bb;
        g_outrow[1][row] = a1 + bb;
        g_outrow[2][row] = a2 + bb;
        g_outrow[3][row] = a3 + bb;
    }
}

__global__ void k_fb_attn(float4* __restrict__ out, unsigned n4,
                          const void* __restrict__ mask) {
    __shared__ int sFloat, sOff;
    __shared__ int scnt[B];
    const int tid = threadIdx.x;
    if (tid == 0) { sFloat = 0; sOff = 0; }
    if (tid < B) scnt[tid] = 0;
    __syncthreads();
    probe_flags(mask, tid, &sFloat, &sOff);
    __syncthreads();
    const int mode = sFloat ? 2 : (sOff ? 1 : 0);
    {
        int c = 0;
        for (int i = 0; i < 16; i++)
            c += mask_test(mask, mode, tid * 16 + i) ? 0 : 1;
        atomicAdd(&scnt[tid >> 6], c);
    }
    __syncthreads();
    unsigned idx = blockIdx.x * blockDim.x + tid;
    if (idx >= n4) return;
    int b = (idx >> 22) & 3;
    float inv = 1.0f / (float)max(scnt[b], 1);
    int k0 = (idx & 255u) * 4;
    float4 v;
    v.x = mask_test(mask, mode, b * L + k0 + 0) ? 0.0f : inv;
    v.y = mask_test(mask, mode, b * L + k0 + 1) ? 0.0f : inv;
    v.z = mask_test(mask, mode, b * L + k0 + 2) ? 0.0f : inv;
    v.w = mask_test(mask, mode, b * L + k0 + 3) ? 0.0f : inv;
    __stcs(out + idx, v);
}
__global__ void k_fb_out(float4* __restrict__ out, unsigned n4) {
    unsigned idx = blockIdx.x * blockDim.x + threadIdx.x;
    if (idx >= n4) return;
    unsigned o4 = idx & 255u;
    unsigned b  = (idx >> 18) & 3u;
    __stcs(out + idx, ((const float4*)g_outrow[b])[o4]);
}

// ---------------------------------------------------------------------------
extern "C" void kernel_launch(void* const* d_in, const int* in_sizes, int n_in,
                              void* d_out, int out_size) {
    const float* value = (const float*)d_in[2];
    const void*  mask  = d_in[3];
    const float* Wv    = (const float*)d_in[8];
    const float* bv    = (const float*)d_in[9];
    const float* Wo    = (const float*)d_in[10];
    const float* bo    = (const float*)d_in[11];
    float* out = (float*)d_out;

    const int OUT_N  = B * L * D;          //  4,194,304
    const int ATTN_N = B * H * L * L;      // 67,108,864

    if (out_size == OUT_N + ATTN_N) {
        k_fused<<<NPREFIX + NBLK_ATTN, 256>>>(value, mask, Wv, bv, Wo, bo,
                                              (float4*)out,
                                              (float4*)(out + OUT_N));
    } else {
        // robustness path (not expected)
        k_colsum<<<NPREFIX, 256>>>(value, mask);
        k_gemv_v<<<128, 256>>>(Wv, bv, mask);
        k_gemv_o<<<128, 256>>>(Wo, bo);
        if (out_size >= OUT_N) {
            unsigned n4o = OUT_N / 4;
            k_fb_out<<<(n4o + 255) / 256, 256>>>((float4*)out, n4o);
            unsigned rem = (unsigned)((out_size - OUT_N) / 4);
            if (rem) {
                if (rem > (unsigned)(ATTN_N / 4)) rem = ATTN_N / 4;
                k_fb_attn<<<(rem + 255) / 256, 256>>>((float4*)(out + OUT_N),
                                                      rem, mask);
            }
        } else {
            unsigned n4o = (unsigned)(out_size / 4);
            if (n4o) k_fb_out<<<(n4o + 255) / 256, 256>>>((float4*)out, n4o);
        }
    }
}